// round 1
// baseline (speedup 1.0000x reference)
#include <cuda_runtime.h>
#include <math.h>

// Problem constants
#define BD 8
#define SD 32
#define ND 16
#define DD 512
#define BSZ 256           // B*S
#define HLY 512
#define P_ITERS 3
#define HL2 512           // HLSTM
#define CD 6

#define NEDGE (BSZ*ND*ND)     // 65536
#define NNODE (BSZ*ND)        // 4096

// ---------------- scratch (static device allocations) ----------------
__device__ float g_edge[(size_t)NEDGE*DD];   // [bs][i][w][d]  128 MB
__device__ float g_me  [(size_t)NEDGE*DD];   // [bs][i][w][m]  128 MB
__device__ float g_mh  [(size_t)NNODE*DD];   // [bs][w][m]
__device__ float g_node[(size_t)NNODE*DD];   // [bs][n][d]
__device__ float g_msum[(size_t)NNODE*DD];   // [bs][i][m]
__device__ float g_gi  [(size_t)NNODE*3*DD];
__device__ float g_gh  [(size_t)NNODE*3*DD];
__device__ float g_adj [NEDGE];
__device__ float g_gate[NEDGE];
__device__ float g_hbuf[BD*ND*HL2];
__device__ float g_cbuf[BD*ND*HL2];
__device__ float g_gbuf[BD*ND*4*HL2];        // [m][2048]

__device__ __forceinline__ float sigf(float x) { return 1.0f / (1.0f + expf(-x)); }

// ---------------- misc ----------------
__global__ void zero_kernel(float* p, int n) {
    int i = blockIdx.x * blockDim.x + threadIdx.x;
    if (i < n) p[i] = 0.0f;
}

// ---------------- prep: transpose + mask ----------------
// node_resnet (B,S,D,N) -> g_node [bs][n][d], zero outside mask
__global__ __launch_bounds__(256) void prep_node(const float* __restrict__ nr,
                                                 const int* __restrict__ nnum) {
    int bs = blockIdx.x;
    __shared__ float s[16 * 522];
    int tid = threadIdx.x;
    const float* src = nr + (size_t)bs * DD * ND;
    #pragma unroll
    for (int it = 0; it < 32; it++) {
        int pos = it * 256 + tid;           // pos = d*16 + n
        int d = pos >> 4, n = pos & 15;
        s[n * 522 + d] = src[pos];
    }
    __syncthreads();
    int nn = nnum[bs];
    float* dst = g_node + (size_t)bs * ND * DD;
    #pragma unroll
    for (int it = 0; it < 32; it++) {
        int pos = it * 256 + tid;           // pos = n*512 + d
        int n = pos >> 9, d = pos & 511;
        dst[pos] = (n < nn) ? s[n * 522 + d] : 0.0f;
    }
}

// edge_resnet (B,S,D,N,N) -> g_edge [bs][i][w][d], zero outside emask&offdiag
__global__ __launch_bounds__(256) void prep_edge(const float* __restrict__ er,
                                                 const int* __restrict__ nnum) {
    int blk = blockIdx.x;                   // bs*16 + i
    int bs = blk >> 4, i = blk & 15;
    __shared__ float s[16 * 522];
    int tid = threadIdx.x;
    const float* src = er + (size_t)bs * DD * ND * ND + i * ND;  // + d*256 + w
    #pragma unroll
    for (int it = 0; it < 32; it++) {
        int pos = it * 256 + tid;           // pos = d*16 + w
        int d = pos >> 4, w = pos & 15;
        s[w * 522 + d] = src[(size_t)d * 256 + w];
    }
    __syncthreads();
    int nn = nnum[bs];
    bool iv = (i < nn);
    float* dst = g_edge + (size_t)blk * ND * DD;
    #pragma unroll
    for (int it = 0; it < 32; it++) {
        int pos = it * 256 + tid;           // pos = w*512 + d
        int w = pos >> 9, d = pos & 511;
        bool keep = iv && (w < nn) && (w != i);
        dst[pos] = keep ? s[w * 522 + d] : 0.0f;
    }
}

// ---------------- generic NT SGEMM ----------------
// C[m][n] = sum_k A[m*lda+k] * Bw[n*ldb+k]   (both K-contiguous)
// BM=BN=128, BK=16, 256 threads, 8x8 per thread. M,Ncols multiples of 128; K mult of 16.
// EPI=0: C += bias (optional), store.
// EPI=1: relu(acc+bias[col])*w2[col], row-reduce, atomicAdd into adjout[row].
template <int EPI>
__global__ __launch_bounds__(256) void sgemm_nt(
    const float* __restrict__ A, int lda,
    const float* __restrict__ Bw, int ldb,
    float* __restrict__ C, int ldc, int K,
    const float* __restrict__ bias,
    const float* __restrict__ w2,
    float* __restrict__ adjout)
{
    __shared__ float As[16][132];
    __shared__ float Bs[16][132];
    int tid = threadIdx.x;
    int tx = tid & 15, ty = tid >> 4;
    int rowBase = blockIdx.y * 128;
    int colBase = blockIdx.x * 128;
    float acc[8][8] = {};

    for (int k0 = 0; k0 < K; k0 += 16) {
        #pragma unroll
        for (int i = 0; i < 2; i++) {
            int pos = tid * 2 + i;          // 0..511 : row = pos>>2, k4 = (pos&3)*4
            int r = pos >> 2, k4 = (pos & 3) * 4;
            float4 v = *(const float4*)(A + (size_t)(rowBase + r) * lda + k0 + k4);
            As[k4 + 0][r] = v.x; As[k4 + 1][r] = v.y;
            As[k4 + 2][r] = v.z; As[k4 + 3][r] = v.w;
            float4 u = *(const float4*)(Bw + (size_t)(colBase + r) * ldb + k0 + k4);
            Bs[k4 + 0][r] = u.x; Bs[k4 + 1][r] = u.y;
            Bs[k4 + 2][r] = u.z; Bs[k4 + 3][r] = u.w;
        }
        __syncthreads();
        #pragma unroll
        for (int kk = 0; kk < 16; kk++) {
            float a[8], b[8];
            #pragma unroll
            for (int i = 0; i < 8; i++) a[i] = As[kk][ty * 8 + i];
            #pragma unroll
            for (int j = 0; j < 8; j++) b[j] = Bs[kk][tx * 8 + j];
            #pragma unroll
            for (int i = 0; i < 8; i++)
                #pragma unroll
                for (int j = 0; j < 8; j++)
                    acc[i][j] += a[i] * b[j];
        }
        __syncthreads();
    }

    if (EPI == 0) {
        #pragma unroll
        for (int i = 0; i < 8; i++) {
            int r = rowBase + ty * 8 + i;
            #pragma unroll
            for (int j = 0; j < 8; j++) {
                int c = colBase + tx * 8 + j;
                float v = acc[i][j];
                if (bias) v += bias[c];
                C[(size_t)r * ldc + c] = v;
            }
        }
    } else {
        float rs[8];
        #pragma unroll
        for (int i = 0; i < 8; i++) {
            float s = 0.0f;
            #pragma unroll
            for (int j = 0; j < 8; j++) {
                int c = colBase + tx * 8 + j;
                float v = fmaxf(acc[i][j] + bias[c], 0.0f);
                s += v * w2[c];
            }
            rs[i] = s;
        }
        __syncthreads();
        float* red = &As[0][0];             // 2112 floats available, need 2048
        #pragma unroll
        for (int i = 0; i < 8; i++) red[(ty * 8 + i) * 16 + tx] = rs[i];
        __syncthreads();
        if (tid < 128) {
            float s = 0.0f;
            #pragma unroll
            for (int j = 0; j < 16; j++) s += red[tid * 16 + j];
            atomicAdd(&adjout[rowBase + tid], s);
        }
    }
}

// ---------------- per-iteration elementwise kernels ----------------
__global__ void gate_kernel(const float* __restrict__ b2,
                            const int* __restrict__ nnum,
                            float* __restrict__ out_adj) {
    int e = blockIdx.x * blockDim.x + threadIdx.x;
    if (e >= NEDGE) return;
    int bs = e >> 8, r = e & 255;
    int i = r >> 4, j = r & 15;
    int nn = nnum[bs];
    bool em = (i < nn) && (j < nn);
    float a = g_adj[e] + b2[0];
    float s = sigf(a);
    g_gate[e] = em ? s : 0.0f;
    out_adj[e] = em ? s : 0.5f;             // sigmoid(0) outside emask
}

__global__ __launch_bounds__(256) void msg_kernel(const float* __restrict__ bm) {
    int blk = blockIdx.x;                   // bs*16 + i
    int bs = blk >> 4, i = blk & 15;
    int tid = threadIdx.x;
    float bm0 = bm[tid], bm1 = bm[tid + 256];
    float a0 = 0.0f, a1 = 0.0f;
    const float* gaterow = g_gate + bs * 256 + i * 16;
    #pragma unroll 4
    for (int w = 0; w < 16; w++) {
        float g = gaterow[w];
        size_t eoff = ((size_t)blk * 16 + w) * DD;
        size_t moff = ((size_t)(bs * 16 + w)) * DD;
        float v0 = g * fmaxf(g_mh[moff + tid]       + g_me[eoff + tid]       + bm0, 0.0f);
        float v1 = g * fmaxf(g_mh[moff + tid + 256] + g_me[eoff + tid + 256] + bm1, 0.0f);
        g_edge[eoff + tid]       = v0;      // edge_state = emask ? msg : 0 (gate==0 outside)
        g_edge[eoff + tid + 256] = v1;
        a0 += v0; a1 += v1;
    }
    g_msum[(size_t)blk * DD + tid]       = a0;
    g_msum[(size_t)blk * DD + tid + 256] = a1;
}

__global__ void gru_kernel(const int* __restrict__ nnum) {
    int idx = blockIdx.x * blockDim.x + threadIdx.x;
    if (idx >= NNODE * DD) return;
    int row = idx >> 9, d = idx & 511;
    int bs = row >> 4, n = row & 15;
    size_t b3 = (size_t)row * 1536;
    float ir = g_gi[b3 + d], iz = g_gi[b3 + 512 + d], inn = g_gi[b3 + 1024 + d];
    float hr = g_gh[b3 + d], hz = g_gh[b3 + 512 + d], hn  = g_gh[b3 + 1024 + d];
    float r = sigf(ir + hr);
    float z = sigf(iz + hz);
    float nt = tanhf(inn + r * hn);
    float old = g_node[idx];
    float hnew = (1.0f - z) * nt + z * old;
    g_node[idx] = (n < nnum[bs]) ? hnew : 0.0f;
}

// ---------------- LSTM ----------------
// G[128][2048] = x_t @ Wl_ih^T + h @ Wl_hh^T + (bih+bhh)
// BM=32, BN=64, BK=16, 128 threads, 4x4 per thread.
__global__ __launch_bounds__(128) void lstm_gemm(
    const float* __restrict__ Wih, const float* __restrict__ Whh,
    const float* __restrict__ bih, const float* __restrict__ bhh, int t)
{
    __shared__ float As[16][36];
    __shared__ float Bs[16][68];
    int tid = threadIdx.x;
    int tx = tid & 15, ty = tid >> 4;       // 16 x 8
    int rowBase = blockIdx.y * 32;
    int colBase = blockIdx.x * 64;
    float acc[4][4] = {};

    #pragma unroll
    for (int phase = 0; phase < 2; phase++) {
        const float* Wsrc = phase ? Whh : Wih;
        for (int k0 = 0; k0 < 512; k0 += 16) {
            {   // A tile: 32 rows x 16 k = 128 float4 -> one per thread
                int pos = tid;
                int r = pos >> 2, k4 = (pos & 3) * 4;
                int m = rowBase + r;
                const float* aptr;
                if (phase == 0) {
                    int b = m >> 4, n = m & 15;
                    aptr = g_node + ((size_t)((b * SD + t) * ND + n)) * DD;
                } else {
                    aptr = g_hbuf + (size_t)m * HL2;
                }
                float4 v = *(const float4*)(aptr + k0 + k4);
                As[k4 + 0][r] = v.x; As[k4 + 1][r] = v.y;
                As[k4 + 2][r] = v.z; As[k4 + 3][r] = v.w;
            }
            #pragma unroll
            for (int i = 0; i < 2; i++) {   // B tile: 64 x 16 = 256 float4 -> 2 each
                int pos = tid * 2 + i;
                int r = pos >> 2, k4 = (pos & 3) * 4;
                float4 u = *(const float4*)(Wsrc + (size_t)(colBase + r) * DD + k0 + k4);
                Bs[k4 + 0][r] = u.x; Bs[k4 + 1][r] = u.y;
                Bs[k4 + 2][r] = u.z; Bs[k4 + 3][r] = u.w;
            }
            __syncthreads();
            #pragma unroll
            for (int kk = 0; kk < 16; kk++) {
                float a[4], b[4];
                #pragma unroll
                for (int i = 0; i < 4; i++) a[i] = As[kk][ty * 4 + i];
                #pragma unroll
                for (int j = 0; j < 4; j++) b[j] = Bs[kk][tx * 4 + j];
                #pragma unroll
                for (int i = 0; i < 4; i++)
                    #pragma unroll
                    for (int j = 0; j < 4; j++)
                        acc[i][j] += a[i] * b[j];
            }
            __syncthreads();
        }
    }
    #pragma unroll
    for (int i = 0; i < 4; i++) {
        int r = rowBase + ty * 4 + i;
        #pragma unroll
        for (int j = 0; j < 4; j++) {
            int c = colBase + tx * 4 + j;
            g_gbuf[(size_t)r * 2048 + c] = acc[i][j] + bih[c] + bhh[c];
        }
    }
}

// elementwise LSTM cell + fused readout (label) for step t
__global__ __launch_bounds__(256) void lstm_post(
    const float* __restrict__ Wr, const float* __restrict__ br,
    const int* __restrict__ nnum, float* __restrict__ out_label, int t)
{
    int m = blockIdx.x;                     // 0..127 : b = m>>4, n = m&15
    int tid = threadIdx.x;
    float pc[6] = {};
    #pragma unroll
    for (int e = 0; e < 2; e++) {
        int hh = tid + e * 256;
        size_t gb = (size_t)m * 2048;
        float ii = g_gbuf[gb + hh];
        float ff = g_gbuf[gb + 512 + hh];
        float gg = g_gbuf[gb + 1024 + hh];
        float oo = g_gbuf[gb + 1536 + hh];
        float cold = g_cbuf[m * HL2 + hh];
        float cn = sigf(ff) * cold + sigf(ii) * tanhf(gg);
        float hn = sigf(oo) * tanhf(cn);
        g_cbuf[m * HL2 + hh] = cn;
        g_hbuf[m * HL2 + hh] = hn;
        #pragma unroll
        for (int cc = 0; cc < 6; cc++) pc[cc] += hn * Wr[cc * HL2 + hh];
    }
    __shared__ float red[6][256];
    #pragma unroll
    for (int cc = 0; cc < 6; cc++) red[cc][tid] = pc[cc];
    __syncthreads();
    for (int s2 = 128; s2 > 0; s2 >>= 1) {
        if (tid < s2) {
            #pragma unroll
            for (int cc = 0; cc < 6; cc++) red[cc][tid] += red[cc][tid + s2];
        }
        __syncthreads();
    }
    if (tid < 6) {
        int b = m >> 4, n = m & 15;
        int bs = b * SD + t;
        bool mk = (n < nnum[bs]);
        out_label[(size_t)(bs * ND + n) * CD + tid] = mk ? (red[tid][0] + br[tid]) : 0.0f;
    }
}

// ---------------- launch ----------------
extern "C" void kernel_launch(void* const* d_in, const int* in_sizes, int n_in,
                              void* d_out, int out_size) {
    const float* node_resnet = (const float*)d_in[0];
    const float* edge_resnet = (const float*)d_in[1];
    const int*   nnum        = (const int*)d_in[2];
    const float* W1   = (const float*)d_in[3];
    const float* b1   = (const float*)d_in[4];
    const float* W2   = (const float*)d_in[5];
    const float* b2   = (const float*)d_in[6];
    const float* Wm   = (const float*)d_in[7];
    const float* bm   = (const float*)d_in[8];
    const float* Wih  = (const float*)d_in[9];
    const float* Whh  = (const float*)d_in[10];
    const float* bih  = (const float*)d_in[11];
    const float* bhh  = (const float*)d_in[12];
    const float* Wlih = (const float*)d_in[13];
    const float* Wlhh = (const float*)d_in[14];
    const float* blih = (const float*)d_in[15];
    const float* blhh = (const float*)d_in[16];
    const float* Wr   = (const float*)d_in[17];
    const float* br   = (const float*)d_in[18];

    float* out_adj   = (float*)d_out;               // (B,S,N,N) = 65536
    float* out_label = (float*)d_out + NEDGE;       // (B,S,N,C) = 24576

    // device addresses of scratch buffers (for the generic GEMM)
    float *p_edge, *p_me, *p_mh, *p_node, *p_msum, *p_gi, *p_gh, *p_adj;
    cudaGetSymbolAddress((void**)&p_edge, g_edge);
    cudaGetSymbolAddress((void**)&p_me,   g_me);
    cudaGetSymbolAddress((void**)&p_mh,   g_mh);
    cudaGetSymbolAddress((void**)&p_node, g_node);
    cudaGetSymbolAddress((void**)&p_msum, g_msum);
    cudaGetSymbolAddress((void**)&p_gi,   g_gi);
    cudaGetSymbolAddress((void**)&p_gh,   g_gh);
    cudaGetSymbolAddress((void**)&p_adj,  g_adj);
    float *p_hbuf, *p_cbuf;
    cudaGetSymbolAddress((void**)&p_hbuf, g_hbuf);
    cudaGetSymbolAddress((void**)&p_cbuf, g_cbuf);

    // prep: masked transposes
    prep_node<<<BSZ, 256>>>(node_resnet, nnum);
    prep_edge<<<NNODE, 256>>>(edge_resnet, nnum);

    // me = E0 @ Wm_e^T   (Wm_e[m][d] = Wm[m*1024 + 512 + d])
    {
        dim3 g(DD / 128, NEDGE / 128);
        sgemm_nt<0><<<g, 256>>>(p_edge, DD, Wm + DD, 2 * DD, p_me, DD, DD,
                                nullptr, nullptr, nullptr);
    }

    for (int p = 0; p < P_ITERS; p++) {
        zero_kernel<<<NEDGE / 256, 256>>>(p_adj, NEDGE);
        // adj: fused relu(E@W1^T + b1) . W2 row-reduce
        {
            dim3 g(HLY / 128, NEDGE / 128);
            sgemm_nt<1><<<g, 256>>>(p_edge, DD, W1, DD, nullptr, 0, DD,
                                    b1, W2, p_adj);
        }
        gate_kernel<<<NEDGE / 256, 256>>>(b2, nnum, out_adj);
        // mh = node @ Wm_h^T
        {
            dim3 g(DD / 128, NNODE / 128);
            sgemm_nt<0><<<g, 256>>>(p_node, DD, Wm, 2 * DD, p_mh, DD, DD,
                                    nullptr, nullptr, nullptr);
        }
        msg_kernel<<<NNODE, 256>>>(bm);
        // GRU gates
        {
            dim3 g(3 * DD / 128, NNODE / 128);
            sgemm_nt<0><<<g, 256>>>(p_msum, DD, Wih, DD, p_gi, 3 * DD, DD,
                                    bih, nullptr, nullptr);
            sgemm_nt<0><<<g, 256>>>(p_node, DD, Whh, DD, p_gh, 3 * DD, DD,
                                    bhh, nullptr, nullptr);
        }
        gru_kernel<<<(NNODE * DD) / 256, 256>>>(nnum);
    }

    // LSTM
    zero_kernel<<<(BD * ND * HL2) / 256, 256>>>(p_hbuf, BD * ND * HL2);
    zero_kernel<<<(BD * ND * HL2) / 256, 256>>>(p_cbuf, BD * ND * HL2);
    for (int t = 0; t < SD; t++) {
        dim3 g(2048 / 64, 128 / 32);
        lstm_gemm<<<g, 128>>>(Wlih, Wlhh, blih, blhh, t);
        lstm_post<<<BD * ND, 256>>>(Wr, br, nnum, out_label, t);
    }
}

// round 8
// speedup vs baseline: 1.5415x; 1.5415x over previous
#include <cuda_runtime.h>
#include <cuda_bf16.h>
#include <math.h>
#include <stdint.h>

// ---------------- problem constants ----------------
#define BD 8
#define SD 32
#define ND 16
#define DD 512
#define BSZ 256           // B*S
#define HLY 512
#define P_ITERS 3
#define HL2 512           // HLSTM
#define CD 6

#define NEDGE (BSZ*ND*ND)     // 65536
#define NNODE (BSZ*ND)        // 4096
#define KSP 1536              // split-bf16 K

// ---------------- scratch ----------------
__device__ __nv_bfloat16 g_edgeb[(size_t)NEDGE*KSP];   // A' edge state   201 MB
__device__ __nv_bfloat16 g_nodeb[(size_t)NNODE*KSP];   // A' node state
__device__ __nv_bfloat16 g_msumb[(size_t)NNODE*KSP];   // A' m_sum
__device__ __nv_bfloat16 g_hsplb[(size_t)BD*ND*KSP];   // A' LSTM h
__device__ __nv_bfloat16 g_W1b [(size_t)HLY*KSP];      // B' weights
__device__ __nv_bfloat16 g_Wmeb[(size_t)DD*KSP];
__device__ __nv_bfloat16 g_Wmhb[(size_t)DD*KSP];
__device__ __nv_bfloat16 g_Wihb[(size_t)3*DD*KSP];
__device__ __nv_bfloat16 g_Whhb[(size_t)3*DD*KSP];
__device__ __nv_bfloat16 g_Wlihb[(size_t)4*HL2*KSP];
__device__ __nv_bfloat16 g_Wlhhb[(size_t)4*HL2*KSP];
__device__ float g_me  [(size_t)NEDGE*DD];             // 128 MB
__device__ float g_mh  [(size_t)NNODE*DD];
__device__ float g_node[(size_t)NNODE*DD];
__device__ float g_gi  [(size_t)NNODE*3*DD];
__device__ float g_gh  [(size_t)NNODE*3*DD];
__device__ float g_gx  [(size_t)NNODE*4*HL2];          // LSTM x-side gates, 32 MB
__device__ float g_gh2 [BD*ND*4*HL2];                  // LSTM h-side gates (per step)
__device__ float g_adj [NEDGE];
__device__ float g_gate[NEDGE];
__device__ float g_cbuf[BD*ND*HL2];

__device__ __forceinline__ float sigf(float x) { return 1.0f / (1.0f + expf(-x)); }

// A' layout per row: [hi(0..511) | lo(512..1023) | hi(1024..1535)]
__device__ __forceinline__ void split_storeA(__nv_bfloat16* base, size_t row, int d, float v) {
    __nv_bfloat16 h = __float2bfloat16(v);
    float lo = v - __bfloat162float(h);
    base[row * KSP + d]        = h;
    base[row * KSP + 512 + d]  = __float2bfloat16(lo);
    base[row * KSP + 1024 + d] = h;
}

// ---------------- PTX helpers ----------------
__device__ __forceinline__ uint32_t smem_u32(const void* p) {
    uint32_t a;
    asm("{ .reg .u64 t; cvta.to.shared.u64 t, %1; cvt.u32.u64 %0, t; }" : "=r"(a) : "l"(p));
    return a;
}
#define CP_ASYNC16(dst, src) \
    asm volatile("cp.async.cg.shared.global [%0], [%1], 16;" :: "r"(dst), "l"(src) : "memory")
#define CP_COMMIT() asm volatile("cp.async.commit_group;" ::: "memory")
#define CP_WAIT1()  asm volatile("cp.async.wait_group 1;" ::: "memory")
#define CP_WAIT0()  asm volatile("cp.async.wait_group 0;" ::: "memory")

#define LDSM_X4(r0,r1,r2,r3,addr) \
    asm volatile("ldmatrix.sync.aligned.m8n8.x4.shared.b16 {%0,%1,%2,%3}, [%4];" \
        : "=r"(r0),"=r"(r1),"=r"(r2),"=r"(r3) : "r"(addr))

#define MMA16816(d, a, b0v, b1v) \
    asm volatile("mma.sync.aligned.m16n8k16.row.col.f32.bf16.bf16.f32 " \
        "{%0,%1,%2,%3},{%4,%5,%6,%7},{%8,%9},{%0,%1,%2,%3};" \
        : "+f"((d)[0]),"+f"((d)[1]),"+f"((d)[2]),"+f"((d)[3]) \
        : "r"((a)[0]),"r"((a)[1]),"r"((a)[2]),"r"((a)[3]),"r"(b0v),"r"(b1v))

// ---------------- split-bf16 HMMA GEMM ----------------
// C[m][n] = sum_k A'[m][k]*B'[n][k], K'=1536, both strides KSP.
// BM=BN=128, BK=32, 256 threads (8 warps, 2x4), warp tile 64x32.
// EPI=0: C = acc (+bias[col]); EPI=1: atomicAdd(adjout[row], sum relu(acc+bias)*w2)
#define LDS 40   // 32 + 8 halves padding

template <int EPI>
__global__ __launch_bounds__(256) void mma_gemm(
    const __nv_bfloat16* __restrict__ A,
    const __nv_bfloat16* __restrict__ Bw,
    float* __restrict__ C, int ldc,
    const float* __restrict__ bias,
    const float* __restrict__ w2,
    float* __restrict__ adjout)
{
    __shared__ __align__(16) __nv_bfloat16 sA[2][128 * LDS];
    __shared__ __align__(16) __nv_bfloat16 sB[2][128 * LDS];
    int tid = threadIdx.x, lane = tid & 31, wid = tid >> 5;
    int wm = wid & 1, wn = wid >> 1;           // 2 x 4 warp grid
    int rowBase = blockIdx.y * 128;
    int colBase = blockIdx.x * 128;
    float acc[4][4][4] = {};

    // cp.async fill of one stage: A and B tiles, 128 rows x 32 halves each
    auto load_tile = [&](int it, int buf) {
        int k0 = it * 32;
        #pragma unroll
        for (int i = 0; i < 2; i++) {
            int c = tid * 2 + i;               // 0..511
            int r = c >> 2, kc = (c & 3) * 8;
            uint32_t dA = smem_u32(&sA[buf][r * LDS + kc]);
            CP_ASYNC16(dA, A + (size_t)(rowBase + r) * KSP + k0 + kc);
            uint32_t dB = smem_u32(&sB[buf][r * LDS + kc]);
            CP_ASYNC16(dB, Bw + (size_t)(colBase + r) * KSP + k0 + kc);
        }
    };

    load_tile(0, 0);
    CP_COMMIT();

    const int NIT = KSP / 32;                  // 48
    for (int it = 0; it < NIT; it++) {
        int buf = it & 1;
        if (it + 1 < NIT) {
            load_tile(it + 1, buf ^ 1);
            CP_COMMIT();
            CP_WAIT1();
        } else {
            CP_WAIT0();
        }
        __syncthreads();

        #pragma unroll
        for (int ks = 0; ks < 2; ks++) {
            uint32_t af[4][4];
            #pragma unroll
            for (int mt = 0; mt < 4; mt++) {
                uint32_t ad = smem_u32(
                    &sA[buf][(wm * 64 + mt * 16 + (lane & 15)) * LDS + ks * 16 + (lane >> 4) * 8]);
                LDSM_X4(af[mt][0], af[mt][1], af[mt][2], af[mt][3], ad);
            }
            // B: non-trans ldmatrix (k-contiguous [n][k] layout = col-major k x n).
            // Block order: r0=(n+0..7,k+0..7) r1=(n+0..7,k+8..15) r2=(n+8..15,k+0..7) r3=(n+8..15,k+8..15)
            uint32_t bf[2][4];
            #pragma unroll
            for (int np = 0; np < 2; np++) {
                int n = wn * 32 + np * 16 + ((lane >> 4) & 1) * 8 + (lane & 7);
                int k = ks * 16 + ((lane >> 3) & 1) * 8;
                uint32_t bdx = smem_u32(&sB[buf][n * LDS + k]);
                LDSM_X4(bf[np][0], bf[np][1], bf[np][2], bf[np][3], bdx);
            }
            #pragma unroll
            for (int mt = 0; mt < 4; mt++)
                #pragma unroll
                for (int nt = 0; nt < 4; nt++)
                    MMA16816(acc[mt][nt], af[mt],
                             bf[nt >> 1][(nt & 1) * 2], bf[nt >> 1][(nt & 1) * 2 + 1]);
        }
        __syncthreads();
    }

    if (EPI == 0) {
        #pragma unroll
        for (int mt = 0; mt < 4; mt++) {
            int r0 = rowBase + wm * 64 + mt * 16 + (lane >> 2);
            #pragma unroll
            for (int nt = 0; nt < 4; nt++) {
                int c0 = colBase + wn * 32 + nt * 8 + (lane & 3) * 2;
                float b0 = 0.f, b1 = 0.f;
                if (bias) { b0 = bias[c0]; b1 = bias[c0 + 1]; }
                C[(size_t)r0 * ldc + c0]           = acc[mt][nt][0] + b0;
                C[(size_t)r0 * ldc + c0 + 1]       = acc[mt][nt][1] + b1;
                C[(size_t)(r0 + 8) * ldc + c0]     = acc[mt][nt][2] + b0;
                C[(size_t)(r0 + 8) * ldc + c0 + 1] = acc[mt][nt][3] + b1;
            }
        }
    } else {
        #pragma unroll
        for (int mt = 0; mt < 4; mt++) {
            float slo = 0.f, shi = 0.f;
            #pragma unroll
            for (int nt = 0; nt < 4; nt++) {
                int c0 = colBase + wn * 32 + nt * 8 + (lane & 3) * 2;
                float b0 = bias[c0], b1 = bias[c0 + 1];
                float v0 = w2[c0], v1 = w2[c0 + 1];
                slo += fmaxf(acc[mt][nt][0] + b0, 0.f) * v0
                     + fmaxf(acc[mt][nt][1] + b1, 0.f) * v1;
                shi += fmaxf(acc[mt][nt][2] + b0, 0.f) * v0
                     + fmaxf(acc[mt][nt][3] + b1, 0.f) * v1;
            }
            slo += __shfl_xor_sync(0xffffffffu, slo, 1);
            slo += __shfl_xor_sync(0xffffffffu, slo, 2);
            shi += __shfl_xor_sync(0xffffffffu, shi, 1);
            shi += __shfl_xor_sync(0xffffffffu, shi, 2);
            if ((lane & 3) == 0) {
                int r = rowBase + wm * 64 + mt * 16 + (lane >> 2);
                atomicAdd(&adjout[r], slo);
                atomicAdd(&adjout[r + 8], shi);
            }
        }
    }
}

// ---------------- misc ----------------
__global__ void zero_kernel(float* p, int n) {
    int i = blockIdx.x * blockDim.x + threadIdx.x;
    if (i < n) p[i] = 0.0f;
}
__global__ void zero_bf16(__nv_bfloat16* p, int n) {
    int i = blockIdx.x * blockDim.x + threadIdx.x;
    if (i < n) p[i] = __float2bfloat16(0.0f);
}

// weight -> B' layout per row: [hi | hi | lo]
__global__ void conv_w(const float* __restrict__ src, int ld, int off,
                       __nv_bfloat16* __restrict__ dst, int total) {
    int idx = blockIdx.x * blockDim.x + threadIdx.x;
    if (idx >= total) return;
    int r = idx >> 9, d = idx & 511;
    float x = src[(size_t)r * ld + off + d];
    __nv_bfloat16 h = __float2bfloat16(x);
    float lo = x - __bfloat162float(h);
    dst[(size_t)r * KSP + d]        = h;
    dst[(size_t)r * KSP + 512 + d]  = h;
    dst[(size_t)r * KSP + 1024 + d] = __float2bfloat16(lo);
}

// ---------------- prep: transpose + mask ----------------
__global__ __launch_bounds__(256) void prep_node(const float* __restrict__ nr,
                                                 const int* __restrict__ nnum) {
    int bs = blockIdx.x;
    __shared__ float s[16 * 522];
    int tid = threadIdx.x;
    const float* src = nr + (size_t)bs * DD * ND;
    #pragma unroll
    for (int it = 0; it < 32; it++) {
        int pos = it * 256 + tid;
        int d = pos >> 4, n = pos & 15;
        s[n * 522 + d] = src[pos];
    }
    __syncthreads();
    int nn = nnum[bs];
    float* dst = g_node + (size_t)bs * ND * DD;
    #pragma unroll
    for (int it = 0; it < 32; it++) {
        int pos = it * 256 + tid;
        int n = pos >> 9, d = pos & 511;
        float v = (n < nn) ? s[n * 522 + d] : 0.0f;
        dst[pos] = v;
        split_storeA(g_nodeb, (size_t)bs * ND + n, d, v);
    }
}

__global__ __launch_bounds__(256) void prep_edge(const float* __restrict__ er,
                                                 const int* __restrict__ nnum) {
    int blk = blockIdx.x;                 // bs*16 + i
    int bs = blk >> 4, i = blk & 15;
    __shared__ float s[16 * 522];
    int tid = threadIdx.x;
    const float* src = er + (size_t)bs * DD * ND * ND + i * ND;
    #pragma unroll
    for (int it = 0; it < 32; it++) {
        int pos = it * 256 + tid;
        int d = pos >> 4, w = pos & 15;
        s[w * 522 + d] = src[(size_t)d * 256 + w];
    }
    __syncthreads();
    int nn = nnum[bs];
    bool iv = (i < nn);
    #pragma unroll
    for (int it = 0; it < 32; it++) {
        int pos = it * 256 + tid;
        int w = pos >> 9, d = pos & 511;
        bool keep = iv && (w < nn) && (w != i);
        float v = keep ? s[w * 522 + d] : 0.0f;
        split_storeA(g_edgeb, (size_t)blk * 16 + w, d, v);
    }
}

// ---------------- per-iteration elementwise ----------------
__global__ void gate_kernel(const float* __restrict__ b2,
                            const int* __restrict__ nnum,
                            float* __restrict__ out_adj) {
    int e = blockIdx.x * blockDim.x + threadIdx.x;
    if (e >= NEDGE) return;
    int bs = e >> 8, r = e & 255;
    int i = r >> 4, j = r & 15;
    int nn = nnum[bs];
    bool em = (i < nn) && (j < nn);
    float a = g_adj[e] + b2[0];
    float s = sigf(a);
    g_gate[e] = em ? s : 0.0f;
    out_adj[e] = em ? s : 0.5f;
}

__global__ __launch_bounds__(256) void msg_kernel(const float* __restrict__ bm, int write_edge) {
    int blk = blockIdx.x;                 // bs*16 + i
    int bs = blk >> 4, i = blk & 15;
    int tid = threadIdx.x;
    float bm0 = bm[tid], bm1 = bm[tid + 256];
    float a0 = 0.0f, a1 = 0.0f;
    const float* gaterow = g_gate + bs * 256 + i * 16;
    #pragma unroll 4
    for (int w = 0; w < 16; w++) {
        float g = gaterow[w];
        size_t eoff = ((size_t)blk * 16 + w) * DD;
        size_t moff = ((size_t)(bs * 16 + w)) * DD;
        float v0 = g * fmaxf(g_mh[moff + tid]       + g_me[eoff + tid]       + bm0, 0.0f);
        float v1 = g * fmaxf(g_mh[moff + tid + 256] + g_me[eoff + tid + 256] + bm1, 0.0f);
        if (write_edge) {
            split_storeA(g_edgeb, (size_t)blk * 16 + w, tid,       v0);
            split_storeA(g_edgeb, (size_t)blk * 16 + w, tid + 256, v1);
        }
        a0 += v0; a1 += v1;
    }
    split_storeA(g_msumb, (size_t)blk, tid,       a0);
    split_storeA(g_msumb, (size_t)blk, tid + 256, a1);
}

__global__ void gru_kernel(const int* __restrict__ nnum) {
    int idx = blockIdx.x * blockDim.x + threadIdx.x;
    if (idx >= NNODE * DD) return;
    int row = idx >> 9, d = idx & 511;
    int bs = row >> 4, n = row & 15;
    size_t b3 = (size_t)row * 1536;
    float ir = g_gi[b3 + d], iz = g_gi[b3 + 512 + d], inn = g_gi[b3 + 1024 + d];
    float hr = g_gh[b3 + d], hz = g_gh[b3 + 512 + d], hn  = g_gh[b3 + 1024 + d];
    float r = sigf(ir + hr);
    float z = sigf(iz + hz);
    float nt = tanhf(inn + r * hn);
    float old = g_node[idx];
    float hnew = (1.0f - z) * nt + z * old;
    float v = (n < nnum[bs]) ? hnew : 0.0f;
    g_node[idx] = v;
    split_storeA(g_nodeb, (size_t)row, d, v);
}

// ---------------- LSTM cell + readout ----------------
__global__ __launch_bounds__(256) void lstm_post(
    const float* __restrict__ blih, const float* __restrict__ blhh,
    const float* __restrict__ Wr, const float* __restrict__ br,
    const int* __restrict__ nnum, float* __restrict__ out_label, int t)
{
    int m = blockIdx.x;                   // 0..127 : b = m>>4, n = m&15
    int tid = threadIdx.x;
    int b = m >> 4, n = m & 15;
    size_t gxoff = ((size_t)((b * SD + t) * ND + n)) * (4 * HL2);
    size_t ghoff = (size_t)m * (4 * HL2);
    float pc[6] = {};
    #pragma unroll
    for (int e = 0; e < 2; e++) {
        int hh = tid + e * 256;
        float ii = g_gx[gxoff + hh]            + g_gh2[ghoff + hh]            + blih[hh]            + blhh[hh];
        float ff = g_gx[gxoff + 512 + hh]      + g_gh2[ghoff + 512 + hh]      + blih[512 + hh]      + blhh[512 + hh];
        float gg = g_gx[gxoff + 1024 + hh]     + g_gh2[ghoff + 1024 + hh]     + blih[1024 + hh]     + blhh[1024 + hh];
        float oo = g_gx[gxoff + 1536 + hh]     + g_gh2[ghoff + 1536 + hh]     + blih[1536 + hh]     + blhh[1536 + hh];
        float cold = g_cbuf[m * HL2 + hh];
        float cn = sigf(ff) * cold + sigf(ii) * tanhf(gg);
        float hn = sigf(oo) * tanhf(cn);
        g_cbuf[m * HL2 + hh] = cn;
        split_storeA(g_hsplb, (size_t)m, hh, hn);
        #pragma unroll
        for (int cc = 0; cc < 6; cc++) pc[cc] += hn * Wr[cc * HL2 + hh];
    }
    __shared__ float red[6][256];
    #pragma unroll
    for (int cc = 0; cc < 6; cc++) red[cc][tid] = pc[cc];
    __syncthreads();
    for (int s2 = 128; s2 > 0; s2 >>= 1) {
        if (tid < s2) {
            #pragma unroll
            for (int cc = 0; cc < 6; cc++) red[cc][tid] += red[cc][tid + s2];
        }
        __syncthreads();
    }
    if (tid < 6) {
        int bs = b * SD + t;
        bool mk = (n < nnum[bs]);
        out_label[(size_t)(bs * ND + n) * CD + tid] = mk ? (red[tid][0] + br[tid]) : 0.0f;
    }
}

// ---------------- launch ----------------
extern "C" void kernel_launch(void* const* d_in, const int* in_sizes, int n_in,
                              void* d_out, int out_size) {
    const float* node_resnet = (const float*)d_in[0];
    const float* edge_resnet = (const float*)d_in[1];
    const int*   nnum        = (const int*)d_in[2];
    const float* W1   = (const float*)d_in[3];
    const float* b1   = (const float*)d_in[4];
    const float* W2   = (const float*)d_in[5];
    const float* b2   = (const float*)d_in[6];
    const float* Wm   = (const float*)d_in[7];
    const float* bm   = (const float*)d_in[8];
    const float* Wih  = (const float*)d_in[9];
    const float* Whh  = (const float*)d_in[10];
    const float* bih  = (const float*)d_in[11];
    const float* bhh  = (const float*)d_in[12];
    const float* Wlih = (const float*)d_in[13];
    const float* Wlhh = (const float*)d_in[14];
    const float* blih = (const float*)d_in[15];
    const float* blhh = (const float*)d_in[16];
    const float* Wr   = (const float*)d_in[17];
    const float* br   = (const float*)d_in[18];

    float* out_adj   = (float*)d_out;               // (B,S,N,N) = 65536
    float* out_label = (float*)d_out + NEDGE;       // (B,S,N,C)

    __nv_bfloat16 *p_edgeb, *p_nodeb, *p_msumb, *p_hsplb;
    __nv_bfloat16 *p_W1b, *p_Wmeb, *p_Wmhb, *p_Wihb, *p_Whhb, *p_Wlihb, *p_Wlhhb;
    cudaGetSymbolAddress((void**)&p_edgeb, g_edgeb);
    cudaGetSymbolAddress((void**)&p_nodeb, g_nodeb);
    cudaGetSymbolAddress((void**)&p_msumb, g_msumb);
    cudaGetSymbolAddress((void**)&p_hsplb, g_hsplb);
    cudaGetSymbolAddress((void**)&p_W1b,  g_W1b);
    cudaGetSymbolAddress((void**)&p_Wmeb, g_Wmeb);
    cudaGetSymbolAddress((void**)&p_Wmhb, g_Wmhb);
    cudaGetSymbolAddress((void**)&p_Wihb, g_Wihb);
    cudaGetSymbolAddress((void**)&p_Whhb, g_Whhb);
    cudaGetSymbolAddress((void**)&p_Wlihb, g_Wlihb);
    cudaGetSymbolAddress((void**)&p_Wlhhb, g_Wlhhb);
    float *p_me, *p_mh, *p_gi, *p_gh, *p_gx, *p_gh2, *p_adj, *p_cbuf;
    cudaGetSymbolAddress((void**)&p_me,   g_me);
    cudaGetSymbolAddress((void**)&p_mh,   g_mh);
    cudaGetSymbolAddress((void**)&p_gi,   g_gi);
    cudaGetSymbolAddress((void**)&p_gh,   g_gh);
    cudaGetSymbolAddress((void**)&p_gx,   g_gx);
    cudaGetSymbolAddress((void**)&p_gh2,  g_gh2);
    cudaGetSymbolAddress((void**)&p_adj,  g_adj);
    cudaGetSymbolAddress((void**)&p_cbuf, g_cbuf);

    // weight conversions to split-bf16 B' layout
    conv_w<<<(HLY * 512) / 256, 256>>>(W1, 512, 0, p_W1b, HLY * 512);
    conv_w<<<(DD * 512) / 256, 256>>>(Wm, 1024, 512, p_Wmeb, DD * 512);
    conv_w<<<(DD * 512) / 256, 256>>>(Wm, 1024, 0,   p_Wmhb, DD * 512);
    conv_w<<<(3 * DD * 512) / 256, 256>>>(Wih, 512, 0, p_Wihb, 3 * DD * 512);
    conv_w<<<(3 * DD * 512) / 256, 256>>>(Whh, 512, 0, p_Whhb, 3 * DD * 512);
    conv_w<<<(4 * HL2 * 512) / 256, 256>>>(Wlih, 512, 0, p_Wlihb, 4 * HL2 * 512);
    conv_w<<<(4 * HL2 * 512) / 256, 256>>>(Wlhh, 512, 0, p_Wlhhb, 4 * HL2 * 512);

    // prep: masked transposes -> split-bf16 operands
    prep_node<<<BSZ, 256>>>(node_resnet, nnum);
    prep_edge<<<NNODE, 256>>>(edge_resnet, nnum);

    // me = E0 @ Wm_e^T
    {
        dim3 g(DD / 128, NEDGE / 128);
        mma_gemm<0><<<g, 256>>>(p_edgeb, p_Wmeb, p_me, DD, nullptr, nullptr, nullptr);
    }

    for (int p = 0; p < P_ITERS; p++) {
        zero_kernel<<<NEDGE / 256, 256>>>(p_adj, NEDGE);
        // adj: fused relu(E@W1^T + b1) . W2 row-reduce
        {
            dim3 g(HLY / 128, NEDGE / 128);
            mma_gemm<1><<<g, 256>>>(p_edgeb, p_W1b, nullptr, 0, b1, W2, p_adj);
        }
        gate_kernel<<<NEDGE / 256, 256>>>(b2, nnum, out_adj);
        // mh = node @ Wm_h^T
        {
            dim3 g(DD / 128, NNODE / 128);
            mma_gemm<0><<<g, 256>>>(p_nodeb, p_Wmhb, p_mh, DD, nullptr, nullptr, nullptr);
        }
        msg_kernel<<<NNODE, 256>>>(bm, (p < P_ITERS - 1) ? 1 : 0);
        // GRU gates
        {
            dim3 g(3 * DD / 128, NNODE / 128);
            mma_gemm<0><<<g, 256>>>(p_msumb, p_Wihb, p_gi, 3 * DD, bih, nullptr, nullptr);
            mma_gemm<0><<<g, 256>>>(p_nodeb, p_Whhb, p_gh, 3 * DD, bhh, nullptr, nullptr);
        }
        gru_kernel<<<(NNODE * DD) / 256, 256>>>(nnum);
    }

    // LSTM: hoist all x_t @ Wl_ih^T into one big GEMM (rows of g_nodeb ARE x rows)
    {
        dim3 g(4 * HL2 / 128, NNODE / 128);
        mma_gemm<0><<<g, 256>>>(p_nodeb, p_Wlihb, p_gx, 4 * HL2, nullptr, nullptr, nullptr);
    }
    zero_kernel<<<(BD * ND * HL2) / 256, 256>>>(p_cbuf, BD * ND * HL2);
    zero_bf16<<<(BD * ND * KSP) / 256, 256>>>(p_hsplb, BD * ND * KSP);
    for (int t = 0; t < SD; t++) {
        dim3 g(4 * HL2 / 128, 1);
        mma_gemm<0><<<g, 256>>>(p_hsplb, p_Wlhhb, p_gh2, 4 * HL2, nullptr, nullptr, nullptr);
        lstm_post<<<BD * ND, 256>>>(blih, blhh, Wr, br, nnum, out_label, t);
    }
}